// round 1
// baseline (speedup 1.0000x reference)
#include <cuda_runtime.h>

// Problem constants (fixed by the dataset)
#define HH   112
#define WW   112
#define CROP 28
#define CW   56            // cropped width/height
#define NPIX (CW * CW)     // 3136
#define BB   128
#define MM   64
#define TT   12
#define HID  64
#define OUTD 36            // 3*T

// Scratch (static device globals; no runtime allocation)
__device__ float g_aux_partial[BB];
__device__ float g_motion_sum;

// ---------------------------------------------------------------------------
// Kernel 1: per-batch BCE-sum over the 56x56 crop.
// Block = one batch. 224 threads = 56 columns x 4 row-quarters (14 rows each).
// Gaussian is separable with integer distances -> shared LUT tab[k]=exp(-k^2/8).
// ---------------------------------------------------------------------------
__global__ __launch_bounds__(224) void aux_kernel(
    const int*   __restrict__ goal_pixel,   // [B,2]   (col,row)
    const int*   __restrict__ obj_list,     // [B,M,2] (col,row)
    const int*   __restrict__ obj_num,      // [B]
    const int*   __restrict__ road_mask,    // [B,112,112]
    const float* __restrict__ logits)       // [B,56,56]
{
    const int b   = blockIdx.x;
    const int tid = threadIdx.x;            // 0..223
    const int ci  = tid % CW;               // column within crop
    const int rq  = tid / CW;               // row quarter 0..3
    const int c   = ci + CROP;              // global column

    __shared__ float tab[128];
    __shared__ int   s_objx[MM];            // row coord of object
    __shared__ int   s_objy[MM];            // col coord of object
    __shared__ float s_warp[8];

    if (tid < 128) {
        float k = (float)tid;
        tab[tid] = __expf(-k * k * 0.125f);
    }
    // load object coords for this batch
    for (int m = tid; m < MM; m += 224) {
        s_objy[m] = obj_list[(b * MM + m) * 2 + 0];  // col
        s_objx[m] = obj_list[(b * MM + m) * 2 + 1];  // row
    }
    int nobj = obj_num[b];
    nobj = nobj < 0 ? 0 : (nobj > MM ? MM : nobj);

    const int yg = goal_pixel[b * 2 + 0];   // goal col
    const int xg = goal_pixel[b * 2 + 1];   // goal row
    __syncthreads();

    // Accumulate object-gaussian sum for this thread's 14 rows (column hoisted)
    float s[14];
    #pragma unroll
    for (int k = 0; k < 14; k++) s[k] = 0.0f;

    for (int m = 0; m < nobj; m++) {
        int dy = c - s_objy[m]; dy = dy < 0 ? -dy : dy; dy = dy > 127 ? 127 : dy;
        const float cf = tab[dy];
        const int ox = s_objx[m];
        #pragma unroll
        for (int k = 0; k < 14; k++) {
            int r  = rq * 14 + k + CROP;
            int dx = r - ox; dx = dx < 0 ? -dx : dx; dx = dx > 127 ? 127 : dx;
            s[k] = fmaf(cf, tab[dx], s[k]);
        }
    }

    // goal column factor
    int dyg = c - yg; dyg = dyg < 0 ? -dyg : dyg; dyg = dyg > 127 ? 127 : dyg;
    const float gcf = tab[dyg];

    float local = 0.0f;
    #pragma unroll
    for (int k = 0; k < 14; k++) {
        const int ri = rq * 14 + k;         // crop row
        const int r  = ri + CROP;           // global row
        const float z = logits[b * NPIX + ri * CW + ci];
        const int road = road_mask[(b * HH + r) * WW + c];
        // softplus(z) = max(z,0) + log(1 + exp(-|z|))
        const float sp = fmaxf(z, 0.0f) + __logf(1.0f + __expf(-fabsf(z)));
        float gt = 0.0f;
        if (road != 0) {
            int dxg = r - xg; dxg = dxg < 0 ? -dxg : dxg; dxg = dxg > 127 ? 127 : dxg;
            const float goal_g = gcf * tab[dxg];
            gt = 0.5f + 0.5f * goal_g - 0.5f * s[k];
        }
        local += sp - z * gt;
    }

    // block reduce (7 warps)
    #pragma unroll
    for (int off = 16; off > 0; off >>= 1)
        local += __shfl_down_sync(0xffffffffu, local, off);
    if ((tid & 31) == 0) s_warp[tid >> 5] = local;
    __syncthreads();
    if (tid == 0) {
        float acc = 0.0f;
        #pragma unroll
        for (int w = 0; w < 7; w++) acc += s_warp[w];
        g_aux_partial[b] = acc;
    }
}

// ---------------------------------------------------------------------------
// Kernel 2: motion loss. One block of 128 threads, thread b = one batch row.
// ---------------------------------------------------------------------------
__global__ __launch_bounds__(BB) void motion_kernel(
    const int*   __restrict__ goal_pixel,       // [B,2]
    const float* __restrict__ target_positions, // [B,T,2]
    const float* __restrict__ target_yaws,      // [B,T]
    const float* __restrict__ w1,               // [2,HID]
    const float* __restrict__ b1,               // [HID]
    const float* __restrict__ w2,               // [HID,OUTD]
    const float* __restrict__ b2)               // [OUTD]
{
    const int b = threadIdx.x;
    const float x0 = (float)goal_pixel[2 * b + 0];
    const float x1 = (float)goal_pixel[2 * b + 1];

    float h[HID];
    #pragma unroll
    for (int j = 0; j < HID; j++) {
        float v = fmaf(x0, w1[j], fmaf(x1, w1[HID + j], b1[j]));
        h[j] = v > 0.0f ? v : 0.0f;
    }

    float sum = 0.0f;
    for (int o = 0; o < OUTD; o++) {
        float acc = b2[o];
        #pragma unroll
        for (int j = 0; j < HID; j++)
            acc = fmaf(h[j], w2[j * OUTD + o], acc);
        const int t = o / 3, u = o % 3;
        const float tgt = (u < 2) ? target_positions[(b * TT + t) * 2 + u]
                                  : target_yaws[b * TT + t];
        const float d = acc - tgt;
        sum = fmaf(d, d, sum);
    }

    __shared__ float s_warp[4];
    #pragma unroll
    for (int off = 16; off > 0; off >>= 1)
        sum += __shfl_down_sync(0xffffffffu, sum, off);
    if ((b & 31) == 0) s_warp[b >> 5] = sum;
    __syncthreads();
    if (b == 0)
        g_motion_sum = s_warp[0] + s_warp[1] + s_warp[2] + s_warp[3];
}

// ---------------------------------------------------------------------------
// Kernel 3: final combine -> out[0]=loss, out[1]=aux, out[2]=motion
// ---------------------------------------------------------------------------
__global__ __launch_bounds__(BB) void final_kernel(float* __restrict__ out)
{
    const int tid = threadIdx.x;   // 128
    float v = g_aux_partial[tid];
    __shared__ float s_warp[4];
    #pragma unroll
    for (int off = 16; off > 0; off >>= 1)
        v += __shfl_down_sync(0xffffffffu, v, off);
    if ((tid & 31) == 0) s_warp[tid >> 5] = v;
    __syncthreads();
    if (tid == 0) {
        const float aux    = s_warp[0] + s_warp[1] + s_warp[2] + s_warp[3];
        const float motion = g_motion_sum * (1.0f / (float)(BB * OUTD));
        out[0] = motion + aux;
        out[1] = aux;
        out[2] = motion;
    }
}

// ---------------------------------------------------------------------------
extern "C" void kernel_launch(void* const* d_in, const int* in_sizes, int n_in,
                              void* d_out, int out_size)
{
    const int*   goal_pixel = (const int*)  d_in[0];
    const int*   obj_list   = (const int*)  d_in[1];
    const int*   obj_num    = (const int*)  d_in[2];
    const int*   road_mask  = (const int*)  d_in[3];
    const float* logits     = (const float*)d_in[4];
    const float* tpos       = (const float*)d_in[5];
    const float* tyaw       = (const float*)d_in[6];
    const float* w1         = (const float*)d_in[7];
    const float* b1         = (const float*)d_in[8];
    const float* w2         = (const float*)d_in[9];
    const float* b2         = (const float*)d_in[10];
    float* out = (float*)d_out;

    aux_kernel<<<BB, 224>>>(goal_pixel, obj_list, obj_num, road_mask, logits);
    motion_kernel<<<1, BB>>>(goal_pixel, tpos, tyaw, w1, b1, w2, b2);
    final_kernel<<<1, BB>>>(out);
}

// round 2
// speedup vs baseline: 2.6616x; 2.6616x over previous
#include <cuda_runtime.h>

// Problem constants
#define HH   112
#define WW   112
#define CROP 28
#define CW   56
#define NPIX (CW * CW)
#define BB   128
#define MM   64
#define TT   12
#define HID  64
#define OUTD 36

#define AUX_BLOCKS 256            // 2 blocks per batch (28 rows each)
#define MOT_BLOCKS 3
#define NBLK (AUX_BLOCKS + MOT_BLOCKS)
#define NTHR 224                  // 56 cols x 4 row-groups of 7 rows

// Scratch (static device globals; no runtime allocation)
__device__ float g_aux_partial[AUX_BLOCKS];
__device__ float g_mot_partial[MOT_BLOCKS];
__device__ int   g_count = 0;

__global__ __launch_bounds__(NTHR) void fused_kernel(
    const int*   __restrict__ goal_pixel,   // [B,2]   (col,row)
    const int*   __restrict__ obj_list,     // [B,M,2] (col,row)
    const int*   __restrict__ obj_num,      // [B]
    const int*   __restrict__ road_mask,    // [B,112,112]
    const float* __restrict__ logits,       // [B,56,56]
    const float* __restrict__ tpos,         // [B,T,2]
    const float* __restrict__ tyaw,         // [B,T]
    const float* __restrict__ w1,           // [2,HID]
    const float* __restrict__ b1,           // [HID]
    const float* __restrict__ w2,           // [HID,OUTD]
    const float* __restrict__ b2,           // [OUTD]
    float*       __restrict__ out)
{
    const int blk = blockIdx.x;
    const int tid = threadIdx.x;

    __shared__ float s_warp[8];
    __shared__ float tabc[232];      // tabc[112+d] = exp(-d^2/8), d in [-112,115]
    __shared__ int2  s_obj[MM];
    __shared__ bool  s_last;

    if (blk < AUX_BLOCKS) {
        // ------------------- aux (BCE over 56x56 crop) -------------------
        const int b   = blk >> 1;
        const int rh  = blk & 1;          // row half: rows [rh*28, rh*28+28)
        const int ci  = tid % CW;         // crop column
        const int g   = tid / CW;         // 0..3 row group
        const int c   = ci + CROP;        // global column
        const int ri0 = rh * 28 + g * 7;  // crop row base (7 rows per thread)
        const int r0  = ri0 + CROP;       // global row base

        for (int i = tid; i < 228; i += NTHR) {
            float d = (float)(i - 112);
            tabc[i] = __expf(-d * d * 0.125f);
        }
        const int2* olist = (const int2*)obj_list;
        for (int m = tid; m < MM; m += NTHR) s_obj[m] = olist[b * MM + m];

        int nobj = obj_num[b];
        nobj = nobj < 0 ? 0 : (nobj > MM ? MM : nobj);
        const int yg = goal_pixel[2 * b + 0];   // goal col
        const int xg = goal_pixel[2 * b + 1];   // goal row
        __syncthreads();

        const float* pcol  = tabc + (c + 112);   // pcol[-oy] = col factor
        const float* prow0 = tabc + (r0 + 112);  // (prow0 - ox)[k] = row factor

        float s[7];
        #pragma unroll
        for (int k = 0; k < 7; k++) s[k] = 0.0f;

        for (int m = 0; m < nobj; m++) {
            const int2 o = s_obj[m];             // x = col(oy), y = row(ox)
            const float cf = pcol[-o.x];
            const float* pr = prow0 - o.y;
            #pragma unroll
            for (int k = 0; k < 7; k++)
                s[k] = fmaf(cf, pr[k], s[k]);
        }

        const float gcf = pcol[-yg];
        const float* pgr = prow0 - xg;

        const float* lgp = logits + b * NPIX + ri0 * CW + ci;
        const int*   rmp = road_mask + (b * HH + r0) * WW + c;

        float local = 0.0f;
        #pragma unroll
        for (int k = 0; k < 7; k++) {
            const float z    = lgp[k * CW];
            const int   road = rmp[k * WW];
            const float sp   = fmaxf(z, 0.0f) + __logf(1.0f + __expf(-fabsf(z)));
            float gt = 0.0f;
            if (road != 0)
                gt = 0.5f + 0.5f * (gcf * pgr[k]) - 0.5f * s[k];
            local += sp - z * gt;
        }

        // block reduce (7 warps)
        #pragma unroll
        for (int off = 16; off > 0; off >>= 1)
            local += __shfl_down_sync(0xffffffffu, local, off);
        if ((tid & 31) == 0) s_warp[tid >> 5] = local;
        __syncthreads();
        if (tid == 0) {
            float acc = 0.0f;
            #pragma unroll
            for (int w = 0; w < 7; w++) acc += s_warp[w];
            g_aux_partial[blk] = acc;
        }
    } else {
        // ------------------- motion MLP loss -------------------
        const int mt = (blk - AUX_BLOCKS) * NTHR + tid;  // 0..671, 512 active
        float part = 0.0f;
        if (mt < BB * 4) {
            const int b  = mt >> 2;
            const int og = mt & 3;          // output group: 9 outputs each

            const float x0 = (float)goal_pixel[2 * b + 0];
            const float x1 = (float)goal_pixel[2 * b + 1];

            float h[HID];
            #pragma unroll
            for (int j = 0; j < HID; j++) {
                float v = fmaf(x0, w1[j], fmaf(x1, w1[HID + j], b1[j]));
                h[j] = fmaxf(v, 0.0f);
            }

            float acc[9];
            #pragma unroll
            for (int u = 0; u < 9; u++) acc[u] = b2[og * 9 + u];

            for (int j = 0; j < HID; j++) {
                const float hv = h[j];
                const float* wr = w2 + j * OUTD + og * 9;
                #pragma unroll
                for (int u = 0; u < 9; u++)
                    acc[u] = fmaf(hv, wr[u], acc[u]);
            }

            #pragma unroll
            for (int u = 0; u < 9; u++) {
                const int o = og * 9 + u;
                const int t = o / 3, uu = o % 3;
                const float tgt = (uu < 2) ? tpos[(b * TT + t) * 2 + uu]
                                           : tyaw[b * TT + t];
                const float d = acc[u] - tgt;
                part = fmaf(d, d, part);
            }
        }
        #pragma unroll
        for (int off = 16; off > 0; off >>= 1)
            part += __shfl_down_sync(0xffffffffu, part, off);
        if ((tid & 31) == 0) s_warp[tid >> 5] = part;
        __syncthreads();
        if (tid == 0) {
            float acc = 0.0f;
            #pragma unroll
            for (int w = 0; w < 7; w++) acc += s_warp[w];
            g_mot_partial[blk - AUX_BLOCKS] = acc;
        }
    }

    // ------------------- last-block-done final combine -------------------
    __syncthreads();
    __threadfence();
    if (tid == 0) {
        int old = atomicAdd(&g_count, 1);
        s_last = (old == NBLK - 1);
    }
    __syncthreads();

    if (s_last) {
        __threadfence();
        float v = 0.0f;
        if (tid < 128)
            v = g_aux_partial[tid] + g_aux_partial[tid + 128];
        #pragma unroll
        for (int off = 16; off > 0; off >>= 1)
            v += __shfl_down_sync(0xffffffffu, v, off);
        if ((tid & 31) == 0) s_warp[tid >> 5] = v;
        __syncthreads();
        if (tid == 0) {
            float aux = s_warp[0] + s_warp[1] + s_warp[2] + s_warp[3];
            float mot = (g_mot_partial[0] + g_mot_partial[1] + g_mot_partial[2])
                        * (1.0f / (float)(BB * OUTD));
            out[0] = mot + aux;
            out[1] = aux;
            out[2] = mot;
            g_count = 0;   // reset for next graph replay
        }
    }
}

extern "C" void kernel_launch(void* const* d_in, const int* in_sizes, int n_in,
                              void* d_out, int out_size)
{
    const int*   goal_pixel = (const int*)  d_in[0];
    const int*   obj_list   = (const int*)  d_in[1];
    const int*   obj_num    = (const int*)  d_in[2];
    const int*   road_mask  = (const int*)  d_in[3];
    const float* logits     = (const float*)d_in[4];
    const float* tpos       = (const float*)d_in[5];
    const float* tyaw       = (const float*)d_in[6];
    const float* w1         = (const float*)d_in[7];
    const float* b1         = (const float*)d_in[8];
    const float* w2         = (const float*)d_in[9];
    const float* b2         = (const float*)d_in[10];
    float* out = (float*)d_out;

    fused_kernel<<<NBLK, NTHR>>>(goal_pixel, obj_list, obj_num, road_mask,
                                 logits, tpos, tyaw, w1, b1, w2, b2, out);
}